// round 9
// baseline (speedup 1.0000x reference)
#include <cuda_runtime.h>

#define NEG_BIG 1e30f

// pitch 260 floats = 1040 B; 1040 mod 128 = 16 -> k consecutive rows hit
// distinct 16B slots (k<=8) => conflict-free LDS.128 with broadcast.
#define PITCHF 260
#define PITCH16 65
#define SPP 66

// Cross-block scratch (zero-init; g_cnt reset by last block each call)
__device__ float    g_pM[256];
__device__ float    g_pSe[256];
__device__ float    g_pSec[256];
__device__ float    g_c1[4096];
__device__ float    g_U[4096];
__device__ unsigned g_cnt[8];

__device__ __forceinline__ void ffma2(unsigned long long& d,
                                      unsigned long long a,
                                      unsigned long long b) {
    asm("fma.rn.f32x2 %0, %1, %2, %0;" : "+l"(d) : "l"(a), "l"(b));
}

union U64f2 { unsigned long long u; float2 f; };

__device__ __forceinline__ float wred_max(float v) {
#pragma unroll
    for (int o = 16; o; o >>= 1) v = fmaxf(v, __shfl_xor_sync(0xffffffffu, v, o));
    return v;
}
__device__ __forceinline__ float wred_sum(float v) {
#pragma unroll
    for (int o = 16; o; o >>= 1) v += __shfl_xor_sync(0xffffffffu, v, o);
    return v;
}

// smem layout (floats)
#define OFF_Q    0                        // 64 * 260 (overlaid by spart later)
#define OFF_CW   (64 * PITCHF)            // 16 * 260
#define OFF_SQC  (OFF_CW + 16 * PITCHF)   // 64
#define OFF_Q1   (OFF_SQC + 64)           // 64
#define OFF_SC   (OFF_Q1 + 64)            // 16
#define OFF_C1   (OFF_SC + 16)            // 16
#define OFF_MS   (OFF_C1 + 16)            // 16
#define OFF_US   (OFF_MS + 16)            // 16
#define SMEM_FLOATS (OFF_US + 16)
#define SMEM_BYTES  (SMEM_FLOATS * 4)     // ~84 KB -> 2 blocks/SM
// spart [4][16][SPP] = 4224 floats, overlaid on Q region (16640 floats)

// Grid (32 i-chunks, 8 batches), 256 threads (8 warps), 2 blocks/SM.
// Block tile 16i x 64j x 256d. Warp: g = w>>1 owns d in [g*64, g*64+64),
// wj = w&1 owns 32 j. Lane li = l>>3 (rows li+4r), lj = l&7 (cols lj+8c).
__global__ __launch_bounds__(256, 2) void attn_fused(
    const float* __restrict__ context,   // (8, 512, 256)
    const float* __restrict__ question,  // (8, 64, 256)
    const int*   __restrict__ maskp,     // (8, 64)
    const float* __restrict__ att_w,     // (768,)
    const float* __restrict__ att_b,     // (1,)
    const float* __restrict__ w_in,      // (256,)
    const float* __restrict__ w_mem,     // (256,)
    float* __restrict__ out)             // (8, 512, 4)
{
    extern __shared__ float sm[];
    float* qs    = sm + OFF_Q;
    float* cws   = sm + OFF_CW;
    float* sqc   = sm + OFF_SQC;
    float* q1sh  = sm + OFF_Q1;
    float* scsh  = sm + OFF_SC;
    float* c1sh  = sm + OFF_C1;
    float* Msh   = sm + OFF_MS;
    float* Ush   = sm + OFF_US;
    float* spart = sm + OFF_Q;           // overlaid after mainloop

    __shared__ int   lastFlag;
    __shared__ float Hs;

    const int b      = blockIdx.y;
    const int blockI = blockIdx.x * 16;
    const int tid    = threadIdx.x;

    const float* qbase = question + (size_t)(b * 64) * 256;
    const float* cbase = context  + (size_t)(b * 512 + blockI) * 256;

    // ---- stage Q tile (64 x 256) + per-j scalars sq, q1 : 4 threads/row ----
    {
        const int jq = tid >> 2;        // 0..63
        const int l4 = tid & 3;
        const float4* qrow = (const float4*)(qbase + (size_t)jq * 256);
        float4* qsrow = (float4*)(qs + jq * PITCHF);
        const float4* wq4 = (const float4*)(att_w + 256);
        const float4* wm4 = (const float4*)(w_mem);
        float sq = 0.f, q1 = 0.f;
#pragma unroll
        for (int k = 0; k < 16; k++) {
            int c4 = l4 + (k << 2);
            float4 v = __ldg(&qrow[c4]);
            qsrow[c4] = v;
            float4 a = __ldg(&wq4[c4]);
            float4 m = __ldg(&wm4[c4]);
            sq += v.x * a.x + v.y * a.y + v.z * a.z + v.w * a.w;
            q1 += v.x * m.x + v.y * m.y + v.z * m.z + v.w * m.w;
        }
        sq += __shfl_xor_sync(0xffffffffu, sq, 1);
        sq += __shfl_xor_sync(0xffffffffu, sq, 2);
        q1 += __shfl_xor_sync(0xffffffffu, q1, 1);
        q1 += __shfl_xor_sync(0xffffffffu, q1, 2);
        if (l4 == 0) {
            float mk = (float)__ldg(&maskp[b * 64 + jq]);
            sqc[jq]  = sq + __ldg(&att_b[0]) - NEG_BIG * (1.0f - mk);
            q1sh[jq] = q1;
        }
    }

    // ---- stage CW tile (16 x 256) + per-i scalars sc, c1 : 16 threads/row ----
    {
        const int ic  = tid >> 4;       // 0..15
        const int l16 = tid & 15;
        const float4* crow = (const float4*)(cbase + (size_t)ic * 256);
        float4* cwrow = (float4*)(cws + ic * PITCHF);
        const float4* wp4 = (const float4*)(att_w + 512);
        const float4* wc4 = (const float4*)(att_w);
        const float4* wi4 = (const float4*)(w_in);
        float sc = 0.f, c1 = 0.f;
#pragma unroll
        for (int k = 0; k < 4; k++) {
            int c4 = l16 + (k << 4);
            float4 v = __ldg(&crow[c4]);
            float4 p = __ldg(&wp4[c4]);
            cwrow[c4] = make_float4(v.x * p.x, v.y * p.y, v.z * p.z, v.w * p.w);
            float4 a = __ldg(&wc4[c4]);
            float4 m = __ldg(&wi4[c4]);
            sc += v.x * a.x + v.y * a.y + v.z * a.z + v.w * a.w;
            c1 += v.x * m.x + v.y * m.y + v.z * m.z + v.w * m.w;
        }
        sc += __shfl_xor_sync(0xffffffffu, sc, 1);
        sc += __shfl_xor_sync(0xffffffffu, sc, 2);
        sc += __shfl_xor_sync(0xffffffffu, sc, 4);
        sc += __shfl_xor_sync(0xffffffffu, sc, 8);
        c1 += __shfl_xor_sync(0xffffffffu, c1, 1);
        c1 += __shfl_xor_sync(0xffffffffu, c1, 2);
        c1 += __shfl_xor_sync(0xffffffffu, c1, 4);
        c1 += __shfl_xor_sync(0xffffffffu, c1, 8);
        if (l16 == 0) { scsh[ic] = sc; c1sh[ic] = c1; }
    }

    __syncthreads();

    // ---- mainloop: S = CW * Q^T, split-d x4, lane tile 4i x 4j ----
    const int w  = tid >> 5;
    const int l  = tid & 31;
    const int g  = w >> 1;      // d-group 0..3
    const int wj = w & 1;       // 0..1 (32 j each)
    const int li = l >> 3;      // 0..3
    const int lj = l & 7;       // 0..7

    const ulonglong2* A0 = (const ulonglong2*)cws + li * PITCH16 + g * 16;
    const ulonglong2* B0 = (const ulonglong2*)qs  + (wj * 32 + lj) * PITCH16 + g * 16;

    unsigned long long acc[4][4];
#pragma unroll
    for (int r = 0; r < 4; r++)
#pragma unroll
        for (int c = 0; c < 4; c++) acc[r][c] = 0ull;

#pragma unroll 4
    for (int d = 0; d < 16; d++) {
        ulonglong2 Ar[4], Bc[4];
#pragma unroll
        for (int r = 0; r < 4; r++) Ar[r] = A0[(r * 4) * PITCH16 + d];
#pragma unroll
        for (int c = 0; c < 4; c++) Bc[c] = B0[(c * 8) * PITCH16 + d];
#pragma unroll
        for (int r = 0; r < 4; r++)
#pragma unroll
            for (int c = 0; c < 4; c++) {
                ffma2(acc[r][c], Ar[r].x, Bc[c].x);
                ffma2(acc[r][c], Ar[r].y, Bc[c].y);
            }
    }

    __syncthreads();   // done reading qs; safe to overlay spart

    // ---- store d-group partials ----
#pragma unroll
    for (int r = 0; r < 4; r++) {
        int row = li + 4 * r;
#pragma unroll
        for (int c = 0; c < 4; c++) {
            int col = wj * 32 + lj + 8 * c;
            U64f2 u; u.u = acc[r][c];
            spart[(g * 16 + row) * SPP + col] = u.f.x + u.f.y;
        }
    }
    __syncthreads();

    // ---- epilogue: warp w owns rows 2w, 2w+1; lane holds j = {2l, 2l+1} ----
    const float2 sq2 = ((const float2*)sqc)[l];
    const float2 q12 = ((const float2*)q1sh)[l];
#pragma unroll
    for (int rr = 0; rr < 2; rr++) {
        int i = 2 * w + rr;
        float2 ps = make_float2(0.f, 0.f);
#pragma unroll
        for (int gg = 0; gg < 4; gg++) {
            float2 t = ((const float2*)spart)[(gg * 16 + i) * (SPP / 2) + l];
            ps.x += t.x; ps.y += t.y;
        }
        float sci = scsh[i];
        float sx = ps.x + sci + sq2.x;
        float sy = ps.y + sci + sq2.y;
        float m = wred_max(fmaxf(sx, sy));
        float ex = __expf(sx - m);
        float ey = __expf(sy - m);
        float se = wred_sum(ex + ey);
        float sn = wred_sum(ex * q12.x + ey * q12.y);
        if (l == 0) {
            Msh[i] = m;
            Ush[i] = sn / se;
        }
    }
    __syncthreads();

    // ---- per-block partial + publish rows; draw ticket ----
    if (tid < 32) {
        float m   = (tid < 16) ? Msh[tid]  : -3.4e38f;
        float c1v = (tid < 16) ? c1sh[tid] : 0.f;
        float Mb  = wred_max(m);
        float e   = __expf(m - Mb);       // lanes >=16 underflow to 0
        float se  = wred_sum(e);
        float sec = wred_sum(e * c1v);
        if (tid == 0) {
            int base = b * 512 + blockI;
            float4* gc = (float4*)(g_c1 + base);
            float4* gu = (float4*)(g_U  + base);
#pragma unroll
            for (int t = 0; t < 4; t++) {
                gc[t] = *(float4*)&c1sh[t * 4];
                gu[t] = *(float4*)&Ush[t * 4];
            }
            int pidx = b * 32 + blockIdx.x;
            g_pM[pidx]   = Mb;
            g_pSe[pidx]  = se;
            g_pSec[pidx] = sec;
            __threadfence();                       // publish before ticket
            unsigned v = atomicAdd(&g_cnt[b], 1u);
            lastFlag = (v == 31u);                 // last block finalizes
        }
    }
    __syncthreads();

    // ---- last block per batch: combine partials, write all 512 rows ----
    if (lastFlag) {
        if (tid < 32) {
            int pidx = b * 32 + tid;
            float mb  = __ldcg(&g_pM[pidx]);
            float se  = __ldcg(&g_pSe[pidx]);
            float sec = __ldcg(&g_pSec[pidx]);
            float M = wred_max(mb);
            float s = __expf(mb - M);
            float seg  = wred_sum(se * s);
            float secg = wred_sum(sec * s);
            if (tid == 0) Hs = secg / seg;
        }
        __syncthreads();
        const float H = Hs;
#pragma unroll
        for (int rr = 0; rr < 2; rr++) {
            int idx = b * 512 + rr * 256 + tid;
            float c1 = __ldcg(&g_c1[idx]);
            float U  = __ldcg(&g_U[idx]);
            ((float4*)out)[idx] = make_float4(c1, U, c1 * U, U * H);
        }
        if (tid == 0) *((volatile unsigned*)&g_cnt[b]) = 0u;  // reset for replay
    }
}

extern "C" void kernel_launch(void* const* d_in, const int* in_sizes, int n_in,
                              void* d_out, int out_size)
{
    const float* context  = (const float*)d_in[0];
    const float* question = (const float*)d_in[1];
    const int*   maskp    = (const int*)d_in[2];
    const float* att_w    = (const float*)d_in[3];
    const float* att_b    = (const float*)d_in[4];
    const float* w_in     = (const float*)d_in[5];
    const float* w_mem    = (const float*)d_in[6];

    cudaFuncSetAttribute(attn_fused,
                         cudaFuncAttributeMaxDynamicSharedMemorySize, SMEM_BYTES);

    dim3 grid(32, 8);
    attn_fused<<<grid, 256, SMEM_BYTES>>>(context, question, maskp,
                                          att_w, att_b, w_in, w_mem,
                                          (float*)d_out);
}

// round 10
// speedup vs baseline: 1.1554x; 1.1554x over previous
#include <cuda_runtime.h>

#define NEG_BIG 1e30f

// pitch 260 floats = 1040 B; 1040 mod 128 = 16 -> k consecutive rows hit
// distinct 16B slots (k<=8) => conflict-free LDS.128 with broadcast.
#define PITCHF 260
#define PITCH16 65
#define SPP 66

// Cross-block scratch (zero-init; g_cnt reset by finalizing block each call)
__device__ float    g_pM[128];
__device__ float    g_pSe[128];
__device__ float    g_pSec[128];
__device__ float    g_c1[4096];
__device__ float    g_U[4096];
__device__ unsigned g_cnt[8];

__device__ __forceinline__ void ffma2(unsigned long long& d,
                                      unsigned long long a,
                                      unsigned long long b) {
    asm("fma.rn.f32x2 %0, %1, %2, %0;" : "+l"(d) : "l"(a), "l"(b));
}

union U64f2 { unsigned long long u; float2 f; };

__device__ __forceinline__ float wred_max(float v) {
#pragma unroll
    for (int o = 16; o; o >>= 1) v = fmaxf(v, __shfl_xor_sync(0xffffffffu, v, o));
    return v;
}
__device__ __forceinline__ float wred_sum(float v) {
#pragma unroll
    for (int o = 16; o; o >>= 1) v += __shfl_xor_sync(0xffffffffu, v, o);
    return v;
}

// smem layout (floats)
#define OFF_Q    0                        // 64 * 260 (overlaid by spart later)
#define OFF_CW   (64 * PITCHF)            // 32 * 260
#define OFF_SQC  (OFF_CW + 32 * PITCHF)   // 64
#define OFF_Q1   (OFF_SQC + 64)           // 64
#define OFF_SC   (OFF_Q1 + 64)            // 32
#define OFF_C1   (OFF_SC + 32)            // 32
#define OFF_MS   (OFF_C1 + 32)            // 32
#define OFF_US   (OFF_MS + 32)            // 32
#define SMEM_FLOATS (OFF_US + 32)
#define SMEM_BYTES  (SMEM_FLOATS * 4)

// Grid (16 i-chunks, 8 batches), 512 threads (16 warps).
// Block tile 32i x 64j x 256d; warp = (d-group g, wi, wj); lane tile 4i x 4j.
// Tail: last block per batch (ticket) combines partials and writes output.
__global__ __launch_bounds__(512) void attn_fused(
    const float* __restrict__ context,   // (8, 512, 256)
    const float* __restrict__ question,  // (8, 64, 256)
    const int*   __restrict__ maskp,     // (8, 64)
    const float* __restrict__ att_w,     // (768,)
    const float* __restrict__ att_b,     // (1,)
    const float* __restrict__ w_in,      // (256,)
    const float* __restrict__ w_mem,     // (256,)
    float* __restrict__ out)             // (8, 512, 4)
{
    extern __shared__ float sm[];
    float* qs    = sm + OFF_Q;
    float* cws   = sm + OFF_CW;
    float* sqc   = sm + OFF_SQC;
    float* q1sh  = sm + OFF_Q1;
    float* scsh  = sm + OFF_SC;
    float* c1sh  = sm + OFF_C1;
    float* Msh   = sm + OFF_MS;
    float* Ush   = sm + OFF_US;
    float* spart = sm + OFF_Q;           // overlaid after mainloop

    __shared__ int   lastFlag;
    __shared__ float Hs;

    const int b      = blockIdx.y;
    const int blockI = blockIdx.x * 32;
    const int tid    = threadIdx.x;

    const float* qbase = question + (size_t)(b * 64) * 256;
    const float* cbase = context  + (size_t)(b * 512 + blockI) * 256;

    // ---- stage Q tile (64 x 256) + per-j scalars sq, q1 : 8 threads/row ----
    {
        const int jq = tid >> 3;        // 0..63
        const int l8 = tid & 7;
        const float4* qrow = (const float4*)(qbase + (size_t)jq * 256);
        float4* qsrow = (float4*)(qs + jq * PITCHF);
        const float4* wq4 = (const float4*)(att_w + 256);
        const float4* wm4 = (const float4*)(w_mem);
        float sq = 0.f, q1 = 0.f;
#pragma unroll
        for (int k = 0; k < 8; k++) {
            int c4 = l8 + (k << 3);
            float4 v = __ldg(&qrow[c4]);
            qsrow[c4] = v;
            float4 a = __ldg(&wq4[c4]);
            float4 m = __ldg(&wm4[c4]);
            sq += v.x * a.x + v.y * a.y + v.z * a.z + v.w * a.w;
            q1 += v.x * m.x + v.y * m.y + v.z * m.z + v.w * m.w;
        }
        sq += __shfl_xor_sync(0xffffffffu, sq, 1);
        sq += __shfl_xor_sync(0xffffffffu, sq, 2);
        sq += __shfl_xor_sync(0xffffffffu, sq, 4);
        q1 += __shfl_xor_sync(0xffffffffu, q1, 1);
        q1 += __shfl_xor_sync(0xffffffffu, q1, 2);
        q1 += __shfl_xor_sync(0xffffffffu, q1, 4);
        if (l8 == 0) {
            float mk = (float)__ldg(&maskp[b * 64 + jq]);
            sqc[jq]  = sq + __ldg(&att_b[0]) - NEG_BIG * (1.0f - mk);
            q1sh[jq] = q1;
        }
    }

    // ---- stage CW tile (32 x 256) + per-i scalars sc, c1 : 16 threads/row ----
    {
        const int ic  = tid >> 4;       // 0..31
        const int l16 = tid & 15;
        const float4* crow = (const float4*)(cbase + (size_t)ic * 256);
        float4* cwrow = (float4*)(cws + ic * PITCHF);
        const float4* wp4 = (const float4*)(att_w + 512);
        const float4* wc4 = (const float4*)(att_w);
        const float4* wi4 = (const float4*)(w_in);
        float sc = 0.f, c1 = 0.f;
#pragma unroll
        for (int k = 0; k < 4; k++) {
            int c4 = l16 + (k << 4);
            float4 v = __ldg(&crow[c4]);
            float4 p = __ldg(&wp4[c4]);
            cwrow[c4] = make_float4(v.x * p.x, v.y * p.y, v.z * p.z, v.w * p.w);
            float4 a = __ldg(&wc4[c4]);
            float4 m = __ldg(&wi4[c4]);
            sc += v.x * a.x + v.y * a.y + v.z * a.z + v.w * a.w;
            c1 += v.x * m.x + v.y * m.y + v.z * m.z + v.w * m.w;
        }
        sc += __shfl_xor_sync(0xffffffffu, sc, 1);
        sc += __shfl_xor_sync(0xffffffffu, sc, 2);
        sc += __shfl_xor_sync(0xffffffffu, sc, 4);
        sc += __shfl_xor_sync(0xffffffffu, sc, 8);
        c1 += __shfl_xor_sync(0xffffffffu, c1, 1);
        c1 += __shfl_xor_sync(0xffffffffu, c1, 2);
        c1 += __shfl_xor_sync(0xffffffffu, c1, 4);
        c1 += __shfl_xor_sync(0xffffffffu, c1, 8);
        if (l16 == 0) { scsh[ic] = sc; c1sh[ic] = c1; }
    }

    __syncthreads();

    // ---- mainloop: S = CW * Q^T, split-d x4, lane tile 4i x 4j ----
    const int w  = tid >> 5;
    const int l  = tid & 31;
    const int g  = w >> 2;      // d-group 0..3
    const int p  = w & 3;
    const int wi = p >> 1;      // 0..1
    const int wj = p & 1;       // 0..1
    const int li = l >> 3;      // 0..3
    const int lj = l & 7;       // 0..7

    const ulonglong2* A0 = (const ulonglong2*)cws + (wi * 16 + li) * PITCH16 + g * 16;
    const ulonglong2* B0 = (const ulonglong2*)qs  + (wj * 32 + lj) * PITCH16 + g * 16;

    unsigned long long acc[4][4];
#pragma unroll
    for (int r = 0; r < 4; r++)
#pragma unroll
        for (int c = 0; c < 4; c++) acc[r][c] = 0ull;

#pragma unroll 4
    for (int d = 0; d < 16; d++) {
        ulonglong2 Ar[4], Bc[4];
#pragma unroll
        for (int r = 0; r < 4; r++) Ar[r] = A0[(r * 4) * PITCH16 + d];
#pragma unroll
        for (int c = 0; c < 4; c++) Bc[c] = B0[(c * 8) * PITCH16 + d];
#pragma unroll
        for (int r = 0; r < 4; r++)
#pragma unroll
            for (int c = 0; c < 4; c++) {
                ffma2(acc[r][c], Ar[r].x, Bc[c].x);
                ffma2(acc[r][c], Ar[r].y, Bc[c].y);
            }
    }

    __syncthreads();   // done reading qs; safe to overlay spart

    // ---- store d-group partials ----
#pragma unroll
    for (int r = 0; r < 4; r++) {
        int row = wi * 16 + li + 4 * r;
#pragma unroll
        for (int c = 0; c < 4; c++) {
            int col = wj * 32 + lj + 8 * c;
            U64f2 u; u.u = acc[r][c];
            spart[(g * 32 + row) * SPP + col] = u.f.x + u.f.y;
        }
    }
    __syncthreads();

    // ---- epilogue: warp w owns rows 2w, 2w+1; lane holds j = {2l, 2l+1} ----
    const float2 sq2 = ((const float2*)sqc)[l];
    const float2 q12 = ((const float2*)q1sh)[l];
#pragma unroll
    for (int rr = 0; rr < 2; rr++) {
        int i = 2 * w + rr;
        float2 ps = make_float2(0.f, 0.f);
#pragma unroll
        for (int gg = 0; gg < 4; gg++) {
            float2 t = ((const float2*)spart)[(gg * 32 + i) * (SPP / 2) + l];
            ps.x += t.x; ps.y += t.y;
        }
        float sci = scsh[i];
        float sx = ps.x + sci + sq2.x;
        float sy = ps.y + sci + sq2.y;
        float m = wred_max(fmaxf(sx, sy));
        float ex = __expf(sx - m);
        float ey = __expf(sy - m);
        float se = wred_sum(ex + ey);
        float sn = wred_sum(ex * q12.x + ey * q12.y);
        if (l == 0) {
            Msh[i] = m;
            Ush[i] = sn / se;
        }
    }
    __syncthreads();

    // ---- publish per-block partial + rows; draw ticket ----
    if (tid < 32) {
        float m   = Msh[tid];
        float c1v = c1sh[tid];
        float Mb  = wred_max(m);
        float e   = __expf(m - Mb);
        float se  = wred_sum(e);
        float sec = wred_sum(e * c1v);
        int idx = b * 512 + blockI + tid;
        g_c1[idx] = c1v;
        g_U[idx]  = Ush[tid];
        if (tid == 0) {
            int pidx = b * 16 + blockIdx.x;
            g_pM[pidx]   = Mb;
            g_pSe[pidx]  = se;
            g_pSec[pidx] = sec;
            __threadfence();                       // publish before ticket
            unsigned v = atomicAdd(&g_cnt[b], 1u);
            lastFlag = (v == 15u);                 // last of 16 finalizes
        }
    }
    __syncthreads();

    // ---- last block of batch: combine 16 partials, write 512 rows ----
    if (lastFlag) {
        if (tid < 32) {
            float mb = -3.4e38f, se = 0.f, sec = 0.f;
            if (tid < 16) {
                int pidx = b * 16 + tid;
                mb  = __ldcg(&g_pM[pidx]);
                se  = __ldcg(&g_pSe[pidx]);
                sec = __ldcg(&g_pSec[pidx]);
            }
            float M = wred_max(mb);
            float s = __expf(mb - M);           // lanes >=16 underflow to 0
            float seg  = wred_sum(se * s);
            float secg = wred_sum(sec * s);
            if (tid == 0) Hs = secg / seg;
        }
        __syncthreads();
        const float H = Hs;
        int idx = b * 512 + tid;                 // 512 threads, 512 rows
        float c1 = __ldcg(&g_c1[idx]);
        float U  = __ldcg(&g_U[idx]);
        ((float4*)out)[idx] = make_float4(c1, U, c1 * U, U * H);
        if (tid == 0) *((volatile unsigned*)&g_cnt[b]) = 0u;  // reset for replay
    }
}

extern "C" void kernel_launch(void* const* d_in, const int* in_sizes, int n_in,
                              void* d_out, int out_size)
{
    const float* context  = (const float*)d_in[0];
    const float* question = (const float*)d_in[1];
    const int*   maskp    = (const int*)d_in[2];
    const float* att_w    = (const float*)d_in[3];
    const float* att_b    = (const float*)d_in[4];
    const float* w_in     = (const float*)d_in[5];
    const float* w_mem    = (const float*)d_in[6];

    cudaFuncSetAttribute(attn_fused,
                         cudaFuncAttributeMaxDynamicSharedMemorySize, SMEM_BYTES);

    dim3 grid(16, 8);
    attn_fused<<<grid, 512, SMEM_BYTES>>>(context, question, maskp,
                                          att_w, att_b, w_in, w_mem,
                                          (float*)d_out);
}